// round 1
// baseline (speedup 1.0000x reference)
#include <cuda_runtime.h>

// PotEnergy1P: out[b] = sum_{i<12, k<64} mask[i,k] * exp(-r)/(r+0.01),
//   r = |x[b,i,:] - neighbors[i,k,:]|
// x: [131072, 24] f32, neighbors: [12,64,2] f32, mask: [12,64] f32.
// MUFU-bound: 3 MUFU (sqrt/ex2/rcp) per pair, 100.7M pairs.

#define NSITES 12
#define NMAX   64
#define NPAIR  (NSITES * NMAX)   // 768

__device__ __forceinline__ float fsqrt_approx(float a) {
    float r;
    asm("sqrt.approx.f32 %0, %1;" : "=f"(r) : "f"(a));
    return r;
}
__device__ __forceinline__ float fex2_approx(float a) {
    float r;
    asm("ex2.approx.f32 %0, %1;" : "=f"(r) : "f"(a));
    return r;
}
__device__ __forceinline__ float frcp_approx(float a) {
    float r;
    asm("rcp.approx.f32 %0, %1;" : "=f"(r) : "f"(a));
    return r;
}

__global__ __launch_bounds__(64)
void pot_energy_kernel(const float* __restrict__ x,
                       const float* __restrict__ nbr,
                       const float* __restrict__ mask,
                       float* __restrict__ out,
                       int batch)
{
    // Geometry packed as {nx, ny, m, pad}: one LDS.128 broadcast per pair.
    __shared__ float4 s_geo[NPAIR];
    for (int j = threadIdx.x; j < NPAIR; j += blockDim.x) {
        s_geo[j] = make_float4(nbr[2 * j], nbr[2 * j + 1], mask[j], 0.0f);
    }
    __syncthreads();

    int b = blockIdx.x * blockDim.x + threadIdx.x;
    if (b >= batch) return;

    // Load 24 floats = 6 x float4 (96B per thread, 16B-aligned).
    float xr[24];
    const float4* xv = reinterpret_cast<const float4*>(x + (size_t)b * 24);
#pragma unroll
    for (int j = 0; j < 6; ++j) {
        float4 v = xv[j];
        xr[4 * j + 0] = v.x;
        xr[4 * j + 1] = v.y;
        xr[4 * j + 2] = v.z;
        xr[4 * j + 3] = v.w;
    }

    const float NEG_L2E = -1.4426950408889634f;  // -log2(e)
    float acc = 0.0f;

#pragma unroll
    for (int i = 0; i < NSITES; ++i) {
        const float xi = xr[2 * i];
        const float yi = xr[2 * i + 1];
        const float4* g = s_geo + i * NMAX;
#pragma unroll 8
        for (int k = 0; k < NMAX; ++k) {
            float4 n = g[k];
            float dx = xi - n.x;
            float dy = yi - n.y;
            float d2 = fmaf(dx, dx, dy * dy);
            float r  = fsqrt_approx(d2);            // MUFU 1
            float e  = fex2_approx(r * NEG_L2E);    // MUFU 2 (exp(-r); FAR -> 0)
            float q  = frcp_approx(r + 0.01f);      // MUFU 3
            acc = fmaf(e * q, n.z, acc);            // mask fused into accumulate
        }
    }
    out[b] = acc;
}

extern "C" void kernel_launch(void* const* d_in, const int* in_sizes, int n_in,
                              void* d_out, int out_size)
{
    const float* x    = (const float*)d_in[0];   // [B, 24]
    const float* nbr  = (const float*)d_in[1];   // [12, 64, 2]
    const float* mask = (const float*)d_in[2];   // [12, 64]
    float* out        = (float*)d_out;           // [B]

    int batch = in_sizes[0] / 24;                // 131072
    const int threads = 64;
    int blocks = (batch + threads - 1) / threads;  // 2048
    pot_energy_kernel<<<blocks, threads>>>(x, nbr, mask, out, batch);
}

// round 2
// speedup vs baseline: 1.3603x; 1.3603x over previous
#include <cuda_runtime.h>

// PotEnergy1P: out[b] = sum_{i<12, k<cnt_i} exp(-r)/(r+0.01),
//   r = |x[b,i,:] - neighbors[i,k,:]|
// MUFU-minimized: 2 MUFU per pair (sqrt, ex2); rcp replaced by bit-trick +
// 2 Newton steps on the FMA pipe. All FMA-pipe math packed f32x2 (2 pairs/op).
// FAR-padded entries self-mask (ex2 underflows to 0), so mask is only used to
// trim the per-site trip count.

#define NSITES 12
#define NMAX   64
#define NGRP   32      // neighbor pairs per site (2 neighbors per group)

typedef unsigned long long u64;

// packed f32x2 constants (same float in both lanes)
#define C_NEGL2E 0xBFB8AA3BBFB8AA3BULL   // -log2(e) = -1.4426950f
#define C_B      0x3C23D70A3C23D70AULL   // 0.01f
#define C_TWO    0x4000000040000000ULL   // 2.0f
#define C_SGN    0x8000000080000000ULL   // per-lane sign bits

__device__ __forceinline__ u64 pk2(float lo, float hi) {
    u64 r; asm("mov.b64 %0, {%1,%2};" : "=l"(r) : "f"(lo), "f"(hi)); return r;
}
__device__ __forceinline__ void upk2(float& lo, float& hi, u64 v) {
    asm("mov.b64 {%0,%1}, %2;" : "=f"(lo), "=f"(hi) : "l"(v));
}
__device__ __forceinline__ u64 addx2(u64 a, u64 b) {
    u64 d; asm("add.rn.f32x2 %0,%1,%2;" : "=l"(d) : "l"(a), "l"(b)); return d;
}
__device__ __forceinline__ u64 mulx2(u64 a, u64 b) {
    u64 d; asm("mul.rn.f32x2 %0,%1,%2;" : "=l"(d) : "l"(a), "l"(b)); return d;
}
__device__ __forceinline__ u64 fmax2(u64 a, u64 b, u64 c) {
    u64 d; asm("fma.rn.f32x2 %0,%1,%2,%3;" : "=l"(d) : "l"(a), "l"(b), "l"(c)); return d;
}
__device__ __forceinline__ float fsqrt_approx(float a) {
    float r; asm("sqrt.approx.f32 %0, %1;" : "=f"(r) : "f"(a)); return r;
}
__device__ __forceinline__ float fex2_approx(float a) {
    float r; asm("ex2.approx.f32 %0, %1;" : "=f"(r) : "f"(a)); return r;
}
__device__ __forceinline__ float rcp_seed(float a) {
    return __int_as_float(0x7EF311C3 - __float_as_int(a));  // ~5% max rel err
}

__global__ __launch_bounds__(64)
void pot_energy_kernel(const float* __restrict__ x,
                       const float* __restrict__ nbr,
                       const float* __restrict__ mask,
                       float* __restrict__ out,
                       int batch)
{
    // Geometry per group of 2 neighbors, pre-negated: {-nx0,-nx1,-ny0,-ny1}
    __shared__ float4 s_geo[NSITES * NGRP];
    __shared__ int    s_ng[NSITES];

    for (int j = threadIdx.x; j < NSITES * NGRP; j += blockDim.x) {
        int base = j * 4;               // = (site*NMAX + 2*g) * 2
        float nx0 = nbr[base + 0], ny0 = nbr[base + 1];
        float nx1 = nbr[base + 2], ny1 = nbr[base + 3];
        s_geo[j] = make_float4(-nx0, -nx1, -ny0, -ny1);
    }
    if (threadIdx.x < NSITES) {
        int c = 0;
        for (int k = 0; k < NMAX; ++k)
            c += (mask[threadIdx.x * NMAX + k] > 0.5f) ? 1 : 0;
        s_ng[threadIdx.x] = (c + 1) >> 1;   // groups of 2 (odd tail self-masks)
    }
    __syncthreads();

    int b = blockIdx.x * blockDim.x + threadIdx.x;
    if (b >= batch) return;

    float xr[24];
    const float4* xv = reinterpret_cast<const float4*>(x + (size_t)b * 24);
#pragma unroll
    for (int j = 0; j < 6; ++j) {
        float4 v = xv[j];
        xr[4 * j + 0] = v.x; xr[4 * j + 1] = v.y;
        xr[4 * j + 2] = v.z; xr[4 * j + 3] = v.w;
    }

    u64 acc = 0ULL;   // packed {0.0f, 0.0f}

#pragma unroll
    for (int i = 0; i < NSITES; ++i) {
        u64 xip = pk2(xr[2 * i],     xr[2 * i]);
        u64 yip = pk2(xr[2 * i + 1], xr[2 * i + 1]);
        const float4* g = s_geo + i * NGRP;
        int ng = s_ng[i];
#pragma unroll 4
        for (int k = 0; k < ng; ++k) {
            float4 q = g[k];                    // LDS.128 broadcast
            u64 nxp = pk2(q.x, q.y);
            u64 nyp = pk2(q.z, q.w);
            u64 dx = addx2(xip, nxp);           // xi - nx (geo pre-negated)
            u64 dy = addx2(yip, nyp);
            u64 d2 = fmax2(dx, dx, mulx2(dy, dy));

            float d2l, d2h; upk2(d2l, d2h, d2);
            float rl = fsqrt_approx(d2l);       // MUFU 1a
            float rh = fsqrt_approx(d2h);       // MUFU 1b
            u64 rp = pk2(rl, rh);

            u64 w    = addx2(rp, C_B);          // r + b
            u64 targ = mulx2(rp, C_NEGL2E);     // -r*log2(e)
            float tl, th; upk2(tl, th, targ);
            float el = fex2_approx(tl);         // MUFU 2a  (FAR -> 0)
            float eh = fex2_approx(th);         // MUFU 2b
            u64 e = pk2(el, eh);

            // 1/(r+b): bit-trick seed + 2 packed Newton steps
            float wl, wh; upk2(wl, wh, w);
            u64 y  = pk2(rcp_seed(wl), rcp_seed(wh));
            u64 wn = w ^ C_SGN;                 // -(r+b), ALU pipe
            u64 t  = fmax2(wn, y, C_TWO);  y = mulx2(y, t);
            t      = fmax2(wn, y, C_TWO);  y = mulx2(y, t);

            acc = fmax2(e, y, acc);             // += exp(-r)/(r+b)
        }
    }

    float al, ah; upk2(al, ah, acc);
    out[b] = al + ah;
}

extern "C" void kernel_launch(void* const* d_in, const int* in_sizes, int n_in,
                              void* d_out, int out_size)
{
    const float* x    = (const float*)d_in[0];   // [B, 24]
    const float* nbr  = (const float*)d_in[1];   // [12, 64, 2]
    const float* mask = (const float*)d_in[2];   // [12, 64]
    float* out        = (float*)d_out;           // [B]

    int batch = in_sizes[0] / 24;
    const int threads = 64;
    int blocks = (batch + threads - 1) / threads;
    pot_energy_kernel<<<blocks, threads>>>(x, nbr, mask, out, batch);
}